// round 5
// baseline (speedup 1.0000x reference)
#include <cuda_runtime.h>
#include <math.h>

#define E_N 100000
#define D_N 300
#define R_N 1000
#define T_N 10000
#define K_N 25
#define SD  320           // padded row stride (floats)
#define D4  75            // 300/4 float4 per real row
#define SD4 80            // 320/4 float4 per padded row
#define GAMMA_F 1.0f

// ---------------- scratch (device globals: allocation-free) ----------------
__device__ float g_emb[(size_t)E_N * SD];
__device__ float g_A1 [(size_t)E_N * SD];
__device__ float g_A2 [(size_t)E_N * SD];
__device__ float g_A3 [(size_t)E_N * SD];
__device__ float g_A4 [(size_t)E_N * SD];
__device__ float g_A5 [(size_t)E_N * SD];
__device__ float g_A6 [(size_t)E_N * SD];
__device__ float g_Lm [R_N * SD];
__device__ float g_Rm [R_N * SD];
__device__ float g_P  [R_N * SD];
__device__ float g_Wt [6 * SD * SD];   // 0:Dt 1:Db1 2:Db2 3:W1 4:W2 5:KG

// ---------------- helpers ----------------
__device__ __forceinline__ float warp_sum(float v) {
#pragma unroll
    for (int o = 16; o > 0; o >>= 1) v += __shfl_xor_sync(0xffffffffu, v, o);
    return v;
}

__device__ __forceinline__ unsigned long long bcast2(float x) {
    unsigned long long r;
    asm("mov.b64 %0, {%1, %1};" : "=l"(r) : "f"(x));
    return r;
}
__device__ __forceinline__ float2 unpack2(unsigned long long v) {
    float2 f;
    asm("mov.b64 {%0, %1}, %2;" : "=f"(f.x), "=f"(f.y) : "l"(v));
    return f;
}
__device__ __forceinline__ void ffma2(unsigned long long& d, unsigned long long a, unsigned long long b) {
    asm("fma.rn.f32x2 %0, %1, %2, %0;" : "+l"(d) : "l"(a), "l"(b));
}
__device__ __forceinline__ void red_add_v4(float* p, float a, float b, float c, float d) {
    asm volatile("red.global.add.v4.f32 [%0], {%1, %2, %3, %4};"
                 :: "l"(p), "f"(a), "f"(b), "f"(c), "f"(d) : "memory");
}

// ---------------- small kernels ----------------
__global__ void zero_out_kernel(float* out) { if (threadIdx.x == 0 && blockIdx.x == 0) out[0] = 0.0f; }

__global__ void zero4_kernel(float4* p, int n4) {
    int i = blockIdx.x * blockDim.x + threadIdx.x;
    if (i < n4) p[i] = make_float4(0.f, 0.f, 0.f, 0.f);
}

__global__ void pad_weights_kernel(const float* __restrict__ Dense,
                                   const float* __restrict__ W1,
                                   const float* __restrict__ W2,
                                   const float* __restrict__ KG) {
    int idx = blockIdx.x * blockDim.x + threadIdx.x;
    const int total = 6 * SD * SD;
    if (idx >= total) return;
    int w   = idx / (SD * SD);
    int rem = idx % (SD * SD);
    int r = rem / SD, c = rem % SD;
    float v = 0.f;
    if (r < D_N && c < D_N) {
        if      (w == 0) v = Dense[(size_t)r * D_N + c];
        else if (w == 1) v = Dense[(size_t)(D_N + r) * D_N + c];
        else if (w == 2) v = Dense[(size_t)(2 * D_N + r) * D_N + c];
        else if (w == 3) v = W1[(size_t)r * D_N + c];
        else if (w == 4) v = W2[(size_t)r * D_N + c];
        else             v = KG[(size_t)r * D_N + c];
    }
    g_Wt[idx] = v;
}

__global__ void normalize_kernel(const float* __restrict__ we) {
    int warp = (blockIdx.x * blockDim.x + threadIdx.x) >> 5;
    int lane = threadIdx.x & 31;
    if (warp >= E_N) return;
    const float4* src = (const float4*)(we + (size_t)warp * D_N);
    float4 v[3];
    float s = 0.f;
#pragma unroll
    for (int it = 0; it < 3; it++) {
        int j = lane + it * 32;
        if (j < D4) {
            float4 x = src[j];
            v[it] = x;
            s += x.x * x.x + x.y * x.y + x.z * x.z + x.w * x.w;
        } else {
            v[it] = make_float4(0.f, 0.f, 0.f, 0.f);
        }
    }
    s = warp_sum(s);
    float inv = 1.0f / sqrtf(s);
    float4* dst = (float4*)(g_emb + (size_t)warp * SD);
#pragma unroll
    for (int it = 0; it < 3; it++) {
        int j = lane + it * 32;
        if (j < D4)       dst[j] = make_float4(v[it].x * inv, v[it].y * inv, v[it].z * inv, v[it].w * inv);
        else if (j < SD4) dst[j] = make_float4(0.f, 0.f, 0.f, 0.f);
    }
}

// COO SpMM scatter with vector reductions. Warp per nnz.
__global__ void spmm_kernel(const int* __restrict__ rows, const int* __restrict__ cols,
                            const float* __restrict__ vals, int nnz,
                            const float* __restrict__ X, float* __restrict__ Out,
                            int rel_mode) {
    int warp = (blockIdx.x * blockDim.x + threadIdx.x) >> 5;
    int lane = threadIdx.x & 31;
    if (warp >= nnz) return;
    int   r = rows[warp];
    int   c = cols[warp];
    float v = vals[warp];
    if (rel_mode && c >= R_N) { c -= R_N; v = -v; }
    const float4* xr = (const float4*)(X + (size_t)c * SD);
    float* orow = Out + (size_t)r * SD;
#pragma unroll
    for (int it = 0; it < 3; it++) {
        int j = lane + it * 32;
        if (j < D4) {
            float4 x = xr[j];
            red_add_v4(orow + j * 4, v * x.x, v * x.y, v * x.z, v * x.w);
        }
    }
}

// ---------------- SGEMM (packed f32x2): C[M,320] (+)= A[M,320] @ B[320,320] ----------------
#define BM 256
#define BN 64
#define BK 16
// grid: x = SD/BN (cols, fast-varying -> L2 reuse of A slab), y = row tiles
__global__ __launch_bounds__(256, 2) void sgemm_kernel(const float* __restrict__ A,
                                                       const float* __restrict__ B,
                                                       float* __restrict__ C,
                                                       int M, int accumulate) {
    __shared__ float As[BK][BM];
    __shared__ float Bs[BK][BN];
    int bm = blockIdx.y * BM;
    int bn = blockIdx.x * BN;
    int tid = threadIdx.x;
    int tx = tid & 7;      // 8 col-groups of 8
    int ty = tid >> 3;     // 32 row-groups of 8
    int arow = bm + tid;
    bool avalid = arow < M;
    const float* Aptr = A + (size_t)arow * SD;
    int brow  = tid >> 4;  // 0..15
    int bcol4 = tid & 15;

    unsigned long long acc[8][4];
#pragma unroll
    for (int i = 0; i < 8; i++)
#pragma unroll
        for (int j = 0; j < 4; j++) acc[i][j] = 0ull;

    for (int k0 = 0; k0 < SD; k0 += BK) {
#pragma unroll
        for (int c = 0; c < 4; c++) {
            float4 a = avalid ? *(const float4*)(Aptr + k0 + c * 4) : make_float4(0.f, 0.f, 0.f, 0.f);
            As[c * 4 + 0][tid] = a.x;
            As[c * 4 + 1][tid] = a.y;
            As[c * 4 + 2][tid] = a.z;
            As[c * 4 + 3][tid] = a.w;
        }
        *(float4*)(&Bs[brow][bcol4 * 4]) =
            *(const float4*)(B + (size_t)(k0 + brow) * SD + bn + bcol4 * 4);
        __syncthreads();
#pragma unroll
        for (int k = 0; k < BK; k++) {
            ulonglong2 bb0 = *(const ulonglong2*)(&Bs[k][tx * 8]);
            ulonglong2 bb1 = *(const ulonglong2*)(&Bs[k][tx * 8 + 4]);
            unsigned long long b2[4] = {bb0.x, bb0.y, bb1.x, bb1.y};
            float4 a0 = *(const float4*)(&As[k][ty * 8]);
            float4 a1 = *(const float4*)(&As[k][ty * 8 + 4]);
            unsigned long long a2[8];
            a2[0] = bcast2(a0.x); a2[1] = bcast2(a0.y); a2[2] = bcast2(a0.z); a2[3] = bcast2(a0.w);
            a2[4] = bcast2(a1.x); a2[5] = bcast2(a1.y); a2[6] = bcast2(a1.z); a2[7] = bcast2(a1.w);
#pragma unroll
            for (int i = 0; i < 8; i++)
#pragma unroll
                for (int j = 0; j < 4; j++)
                    ffma2(acc[i][j], a2[i], b2[j]);
        }
        __syncthreads();
    }
#pragma unroll
    for (int i = 0; i < 8; i++) {
        int grow = bm + ty * 8 + i;
        if (grow < M) {
            float* crow = C + (size_t)grow * SD + bn + tx * 8;
            float2 u0 = unpack2(acc[i][0]);
            float2 u1 = unpack2(acc[i][1]);
            float2 u2 = unpack2(acc[i][2]);
            float2 u3 = unpack2(acc[i][3]);
            float4 o0 = make_float4(u0.x, u0.y, u1.x, u1.y);
            float4 o1 = make_float4(u2.x, u2.y, u3.x, u3.y);
            if (accumulate) {
                float4 c0 = *(float4*)crow;
                float4 c1 = *(float4*)(crow + 4);
                o0 = make_float4(o0.x + c0.x, o0.y + c0.y, o0.z + c0.z, o0.w + c0.w);
                o1 = make_float4(o1.x + c1.x, o1.y + c1.y, o1.z + c1.z, o1.w + c1.w);
            }
            *(float4*)crow       = o0;
            *(float4*)(crow + 4) = o1;
        }
    }
}

// h = emb + relu(h_pre + Bias); pads -> 0.
__global__ void h_kernel(const float* __restrict__ Bias) {
    size_t i = (size_t)blockIdx.x * blockDim.x + threadIdx.x;
    if (i >= (size_t)E_N * SD) return;
    int d = (int)(i % SD);
    if (d < D_N) {
        float pre = g_A1[i] + Bias[d];
        g_A2[i] = g_emb[i] + fmaxf(pre, 0.f);
    } else {
        g_A2[i] = 0.f;
    }
}

__global__ void highway_kernel(const float* __restrict__ bg,
                               const float* __restrict__ L1buf,
                               const float* __restrict__ Gbuf,
                               const float* __restrict__ GCNbuf,
                               float* __restrict__ Outbuf) {
    size_t i = (size_t)blockIdx.x * blockDim.x + threadIdx.x;
    if (i >= (size_t)E_N * SD) return;
    int d = (int)(i % SD);
    if (d < D_N) {
        float tg = 1.0f / (1.0f + expf(-(Gbuf[i] + bg[d])));
        float l2 = fmaxf(GCNbuf[i], 0.f);
        Outbuf[i] = tg * l2 + (1.0f - tg) * L1buf[i];
    } else {
        Outbuf[i] = 0.f;
    }
}

// Fused hinge loss: one block per pair t. l_x/r_x cached in smem, Dm inline,
// 25 negatives split over 8 warps; one atomicAdd per block.
__global__ __launch_bounds__(256) void loss_kernel(const int* __restrict__ pl,
                                                   const int* __restrict__ pr,
                                                   const int* __restrict__ nr,
                                                   const int* __restrict__ nl,
                                                   const float* __restrict__ mask,
                                                   const float* __restrict__ node,
                                                   float* __restrict__ out) {
    __shared__ float4 sl[D4], sr[D4];
    __shared__ float wpart[8];
    __shared__ float s_dm;
    int t    = blockIdx.x;
    int tid  = threadIdx.x;
    int lane = tid & 31;
    int wid  = tid >> 5;

    const float4* xl = (const float4*)(node + (size_t)pl[t] * SD);
    const float4* xr = (const float4*)(node + (size_t)pr[t] * SD);
    float d = 0.f;
    if (tid < D4) {
        float4 a = xl[tid], b = xr[tid];
        sl[tid] = a; sr[tid] = b;
        d = fabsf(a.x - b.x) + fabsf(a.y - b.y) + fabsf(a.z - b.z) + fabsf(a.w - b.w);
    }
    d = warp_sum(d);
    if (lane == 0) wpart[wid] = d;
    __syncthreads();
    if (tid == 0) s_dm = wpart[0] + wpart[1] + wpart[2] + GAMMA_F;
    __syncthreads();
    float dm = s_dm;

    float hsum = 0.f;
    for (int k = wid; k < K_N; k += 8) {
        int i = t * K_N + k;
        const float4* xR = (const float4*)(node + (size_t)nr[i] * SD);
        const float4* xL = (const float4*)(node + (size_t)nl[i] * SD);
        float s1 = 0.f, s2 = 0.f;
#pragma unroll
        for (int it = 0; it < 3; it++) {
            int j = lane + it * 32;
            if (j < D4) {
                float4 a = sl[j], b = sr[j], cr = xR[j], cl = xL[j];
                s1 += fabsf(a.x - cr.x) + fabsf(a.y - cr.y) + fabsf(a.z - cr.z) + fabsf(a.w - cr.w);
                s2 += fabsf(cl.x - b.x) + fabsf(cl.y - b.y) + fabsf(cl.z - b.z) + fabsf(cl.w - b.w);
            }
        }
        s1 = warp_sum(s1);
        s2 = warp_sum(s2);
        if (lane == 0) hsum += (fmaxf(dm - s1, 0.f) + fmaxf(dm - s2, 0.f)) * mask[i];
    }
    if (lane == 0) wpart[wid] = hsum;
    __syncthreads();
    if (tid == 0) {
        float tot = 0.f;
#pragma unroll
        for (int w = 0; w < 8; w++) tot += wpart[w];
        atomicAdd(out, tot * 0.5f);
    }
}

// ---------------- host ----------------
extern "C" void kernel_launch(void* const* d_in, const int* in_sizes, int n_in,
                              void* d_out, int out_size) {
    const float* we    = (const float*)d_in[0];
    const float* kgw   = (const float*)d_in[1];
    const float* bg    = (const float*)d_in[2];
    const float* W1    = (const float*)d_in[3];
    const float* W2    = (const float*)d_in[4];
    const float* Dense = (const float*)d_in[5];
    const float* Bias  = (const float*)d_in[6];
    const int*   hr_rows = (const int*)d_in[7];
    const int*   hr_cols = (const int*)d_in[8];
    const float* hr_vals = (const float*)d_in[9];
    const int*   tr_rows = (const int*)d_in[10];
    const int*   tr_cols = (const int*)d_in[11];
    const float* tr_vals = (const float*)d_in[12];
    const int*   er_rows = (const int*)d_in[13];
    const int*   er_cols = (const int*)d_in[14];
    const float* er_vals = (const float*)d_in[15];
    const int*   adj_rows = (const int*)d_in[16];
    const int*   adj_cols = (const int*)d_in[17];
    const float* adj_vals = (const float*)d_in[18];
    const int*   pos_left  = (const int*)d_in[19];
    const int*   pos_right = (const int*)d_in[20];
    const int*   neg_right = (const int*)d_in[21];
    const int*   neg_left  = (const int*)d_in[22];
    const float* mask      = (const float*)d_in[23];
    float* out = (float*)d_out;

    int nnz_hr  = in_sizes[7];
    int nnz_tr  = in_sizes[10];
    int nnz_er  = in_sizes[13];
    int nnz_adj = in_sizes[16];

    float *p_emb, *p_A1, *p_A2, *p_A3, *p_A4, *p_A5, *p_A6, *p_Lm, *p_Rm, *p_P, *p_Wt;
    cudaGetSymbolAddress((void**)&p_emb, g_emb);
    cudaGetSymbolAddress((void**)&p_A1,  g_A1);
    cudaGetSymbolAddress((void**)&p_A2,  g_A2);
    cudaGetSymbolAddress((void**)&p_A3,  g_A3);
    cudaGetSymbolAddress((void**)&p_A4,  g_A4);
    cudaGetSymbolAddress((void**)&p_A5,  g_A5);
    cudaGetSymbolAddress((void**)&p_A6,  g_A6);
    cudaGetSymbolAddress((void**)&p_Lm,  g_Lm);
    cudaGetSymbolAddress((void**)&p_Rm,  g_Rm);
    cudaGetSymbolAddress((void**)&p_P,   g_P);
    cudaGetSymbolAddress((void**)&p_Wt,  g_Wt);

    const int ELEM = E_N * SD;
    const int EW_BLOCKS = (ELEM + 255) / 256;
    dim3 gemmGridE(SD / BN, (E_N + BM - 1) / BM);   // (5, 391): cols fast -> A reuse in L2
    dim3 gemmGridR(SD / BN, (R_N + BM - 1) / BM);   // (5, 4)

    zero_out_kernel<<<1, 1>>>(out);
    pad_weights_kernel<<<(6 * SD * SD + 255) / 256, 256>>>(Dense, W1, W2, kgw);
    normalize_kernel<<<(E_N * 32) / 256, 256>>>(we);

    // relation aggregation: L, Rm
    zero4_kernel<<<(R_N * SD / 4 + 255) / 256, 256>>>((float4*)p_Lm, R_N * SD / 4);
    zero4_kernel<<<(R_N * SD / 4 + 255) / 256, 256>>>((float4*)p_Rm, R_N * SD / 4);
    spmm_kernel<<<(nnz_hr + 7) / 8, 256>>>(hr_rows, hr_cols, hr_vals, nnz_hr, p_emb, p_Lm, 0);
    spmm_kernel<<<(nnz_tr + 7) / 8, 256>>>(tr_rows, tr_cols, tr_vals, nnz_tr, p_emb, p_Rm, 0);

    // P = L @ Db1 + Rm @ Db2  (Dense_bot pushed through the er-spmm)
    sgemm_kernel<<<gemmGridR, 256>>>(p_Lm, p_Wt + 1 * SD * SD, p_P, R_N, 0);
    sgemm_kernel<<<gemmGridR, 256>>>(p_Rm, p_Wt + 2 * SD * SD, p_P, R_N, 1);

    // h_pre = emb @ Dense_top + spmm(er, +-P)
    sgemm_kernel<<<gemmGridE, 256>>>(p_emb, p_Wt + 0 * SD * SD, p_A1, E_N, 0);
    spmm_kernel<<<(nnz_er + 7) / 8, 256>>>(er_rows, er_cols, er_vals, nnz_er, p_P, p_A1, 1);

    // h = emb + relu(h_pre + Bias)
    h_kernel<<<EW_BLOCKS, 256>>>(Bias);

    // layer 1
    sgemm_kernel<<<gemmGridE, 256>>>(p_A2, p_Wt + 3 * SD * SD, p_A3, E_N, 0);
    sgemm_kernel<<<gemmGridE, 256>>>(p_A2, p_Wt + 5 * SD * SD, p_A4, E_N, 0);
    zero4_kernel<<<(ELEM / 4 + 255) / 256, 256>>>((float4*)p_A5, ELEM / 4);
    spmm_kernel<<<(nnz_adj + 7) / 8, 256>>>(adj_rows, adj_cols, adj_vals, nnz_adj, p_A3, p_A5, 0);
    highway_kernel<<<EW_BLOCKS, 256>>>(bg, p_A2, p_A4, p_A5, p_A6);

    // layer 2
    sgemm_kernel<<<gemmGridE, 256>>>(p_A6, p_Wt + 4 * SD * SD, p_A3, E_N, 0);
    sgemm_kernel<<<gemmGridE, 256>>>(p_A6, p_Wt + 5 * SD * SD, p_A4, E_N, 0);
    zero4_kernel<<<(ELEM / 4 + 255) / 256, 256>>>((float4*)p_A1, ELEM / 4);
    spmm_kernel<<<(nnz_adj + 7) / 8, 256>>>(adj_rows, adj_cols, adj_vals, nnz_adj, p_A3, p_A1, 0);
    highway_kernel<<<EW_BLOCKS, 256>>>(bg, p_A6, p_A4, p_A1, p_A2);   // node -> g_A2

    // fused loss (Dm inline)
    loss_kernel<<<T_N, 256>>>(pos_left, pos_right, neg_right, neg_left, mask, p_A2, out);
    (void)n_in; (void)out_size;
}

// round 6
// speedup vs baseline: 1.0002x; 1.0002x over previous
#include <cuda_runtime.h>
#include <math.h>

#define E_N 100000
#define D_N 300
#define R_N 1000
#define T_N 10000
#define K_N 25
#define SD  320           // padded row stride (floats)
#define D4  75            // 300/4 float4 per real row
#define SD4 80            // 320/4 float4 per padded row
#define GAMMA_F 1.0f

// ---------------- scratch (device globals: allocation-free) ----------------
__device__ float g_emb[(size_t)E_N * SD];
__device__ float g_A1 [(size_t)E_N * SD];
__device__ float g_A2 [(size_t)E_N * SD];
__device__ float g_A3 [(size_t)E_N * SD];
__device__ float g_A4 [(size_t)E_N * SD];
__device__ float g_A5 [(size_t)E_N * SD];
__device__ float g_A6 [(size_t)E_N * SD];
__device__ float g_Lm [R_N * SD];
__device__ float g_Rm [R_N * SD];
__device__ float g_P  [R_N * SD];
__device__ float g_Wt [6 * SD * SD];   // 0:Dt 1:Db1 2:Db2 3:W1 4:W2 5:KG

// ---------------- helpers ----------------
__device__ __forceinline__ float warp_sum(float v) {
#pragma unroll
    for (int o = 16; o > 0; o >>= 1) v += __shfl_xor_sync(0xffffffffu, v, o);
    return v;
}

__device__ __forceinline__ unsigned long long bcast2(float x) {
    unsigned long long r;
    asm("mov.b64 %0, {%1, %1};" : "=l"(r) : "f"(x));
    return r;
}
__device__ __forceinline__ float2 unpack2(unsigned long long v) {
    float2 f;
    asm("mov.b64 {%0, %1}, %2;" : "=f"(f.x), "=f"(f.y) : "l"(v));
    return f;
}
__device__ __forceinline__ void ffma2(unsigned long long& d, unsigned long long a, unsigned long long b) {
    asm("fma.rn.f32x2 %0, %1, %2, %0;" : "+l"(d) : "l"(a), "l"(b));
}
__device__ __forceinline__ void red_add_v4(float* p, float a, float b, float c, float d) {
    asm volatile("red.global.add.v4.f32 [%0], {%1, %2, %3, %4};"
                 :: "l"(p), "f"(a), "f"(b), "f"(c), "f"(d) : "memory");
}

// ---------------- small kernels ----------------
__global__ void zero_out_kernel(float* out) { if (threadIdx.x == 0 && blockIdx.x == 0) out[0] = 0.0f; }

__global__ void zero4_kernel(float4* p, int n4) {
    int i = blockIdx.x * blockDim.x + threadIdx.x;
    if (i < n4) p[i] = make_float4(0.f, 0.f, 0.f, 0.f);
}

__global__ void pad_weights_kernel(const float* __restrict__ Dense,
                                   const float* __restrict__ W1,
                                   const float* __restrict__ W2,
                                   const float* __restrict__ KG) {
    int idx = blockIdx.x * blockDim.x + threadIdx.x;
    const int total = 6 * SD * SD;
    if (idx >= total) return;
    int w   = idx / (SD * SD);
    int rem = idx % (SD * SD);
    int r = rem / SD, c = rem % SD;
    float v = 0.f;
    if (r < D_N && c < D_N) {
        if      (w == 0) v = Dense[(size_t)r * D_N + c];
        else if (w == 1) v = Dense[(size_t)(D_N + r) * D_N + c];
        else if (w == 2) v = Dense[(size_t)(2 * D_N + r) * D_N + c];
        else if (w == 3) v = W1[(size_t)r * D_N + c];
        else if (w == 4) v = W2[(size_t)r * D_N + c];
        else             v = KG[(size_t)r * D_N + c];
    }
    g_Wt[idx] = v;
}

__global__ void normalize_kernel(const float* __restrict__ we) {
    int warp = (blockIdx.x * blockDim.x + threadIdx.x) >> 5;
    int lane = threadIdx.x & 31;
    if (warp >= E_N) return;
    const float4* src = (const float4*)(we + (size_t)warp * D_N);
    float4 v[3];
    float s = 0.f;
#pragma unroll
    for (int it = 0; it < 3; it++) {
        int j = lane + it * 32;
        if (j < D4) {
            float4 x = src[j];
            v[it] = x;
            s += x.x * x.x + x.y * x.y + x.z * x.z + x.w * x.w;
        } else {
            v[it] = make_float4(0.f, 0.f, 0.f, 0.f);
        }
    }
    s = warp_sum(s);
    float inv = 1.0f / sqrtf(s);
    float4* dst = (float4*)(g_emb + (size_t)warp * SD);
#pragma unroll
    for (int it = 0; it < 3; it++) {
        int j = lane + it * 32;
        if (j < D4)       dst[j] = make_float4(v[it].x * inv, v[it].y * inv, v[it].z * inv, v[it].w * inv);
        else if (j < SD4) dst[j] = make_float4(0.f, 0.f, 0.f, 0.f);
    }
}

// COO SpMM scatter with vector reductions. Warp per nnz.
__global__ void spmm_kernel(const int* __restrict__ rows, const int* __restrict__ cols,
                            const float* __restrict__ vals, int nnz,
                            const float* __restrict__ X, float* __restrict__ Out,
                            int rel_mode) {
    int warp = (blockIdx.x * blockDim.x + threadIdx.x) >> 5;
    int lane = threadIdx.x & 31;
    if (warp >= nnz) return;
    int   r = rows[warp];
    int   c = cols[warp];
    float v = vals[warp];
    if (rel_mode && c >= R_N) { c -= R_N; v = -v; }
    const float4* xr = (const float4*)(X + (size_t)c * SD);
    float* orow = Out + (size_t)r * SD;
#pragma unroll
    for (int it = 0; it < 3; it++) {
        int j = lane + it * 32;
        if (j < D4) {
            float4 x = xr[j];
            red_add_v4(orow + j * 4, v * x.x, v * x.y, v * x.z, v * x.w);
        }
    }
}

// ---------------- SGEMM (packed f32x2): C[M,320] (+)= A[M,320] @ B[320,320] ----------------
#define BM 256
#define BN 64
#define BK 16
// grid: x = SD/BN (cols, fast-varying -> L2 reuse of A slab), y = row tiles
__global__ __launch_bounds__(256, 2) void sgemm_kernel(const float* __restrict__ A,
                                                       const float* __restrict__ B,
                                                       float* __restrict__ C,
                                                       int M, int accumulate) {
    __shared__ float As[BK][BM];
    __shared__ float Bs[BK][BN];
    int bm = blockIdx.y * BM;
    int bn = blockIdx.x * BN;
    int tid = threadIdx.x;
    int tx = tid & 7;      // 8 col-groups of 8
    int ty = tid >> 3;     // 32 row-groups of 8
    int arow = bm + tid;
    bool avalid = arow < M;
    const float* Aptr = A + (size_t)arow * SD;
    int brow  = tid >> 4;  // 0..15
    int bcol4 = tid & 15;

    unsigned long long acc[8][4];
#pragma unroll
    for (int i = 0; i < 8; i++)
#pragma unroll
        for (int j = 0; j < 4; j++) acc[i][j] = 0ull;

    for (int k0 = 0; k0 < SD; k0 += BK) {
#pragma unroll
        for (int c = 0; c < 4; c++) {
            float4 a = avalid ? *(const float4*)(Aptr + k0 + c * 4) : make_float4(0.f, 0.f, 0.f, 0.f);
            As[c * 4 + 0][tid] = a.x;
            As[c * 4 + 1][tid] = a.y;
            As[c * 4 + 2][tid] = a.z;
            As[c * 4 + 3][tid] = a.w;
        }
        *(float4*)(&Bs[brow][bcol4 * 4]) =
            *(const float4*)(B + (size_t)(k0 + brow) * SD + bn + bcol4 * 4);
        __syncthreads();
#pragma unroll
        for (int k = 0; k < BK; k++) {
            ulonglong2 bb0 = *(const ulonglong2*)(&Bs[k][tx * 8]);
            ulonglong2 bb1 = *(const ulonglong2*)(&Bs[k][tx * 8 + 4]);
            unsigned long long b2[4] = {bb0.x, bb0.y, bb1.x, bb1.y};
            float4 a0 = *(const float4*)(&As[k][ty * 8]);
            float4 a1 = *(const float4*)(&As[k][ty * 8 + 4]);
            unsigned long long a2[8];
            a2[0] = bcast2(a0.x); a2[1] = bcast2(a0.y); a2[2] = bcast2(a0.z); a2[3] = bcast2(a0.w);
            a2[4] = bcast2(a1.x); a2[5] = bcast2(a1.y); a2[6] = bcast2(a1.z); a2[7] = bcast2(a1.w);
#pragma unroll
            for (int i = 0; i < 8; i++)
#pragma unroll
                for (int j = 0; j < 4; j++)
                    ffma2(acc[i][j], a2[i], b2[j]);
        }
        __syncthreads();
    }
#pragma unroll
    for (int i = 0; i < 8; i++) {
        int grow = bm + ty * 8 + i;
        if (grow < M) {
            float* crow = C + (size_t)grow * SD + bn + tx * 8;
            float2 u0 = unpack2(acc[i][0]);
            float2 u1 = unpack2(acc[i][1]);
            float2 u2 = unpack2(acc[i][2]);
            float2 u3 = unpack2(acc[i][3]);
            float4 o0 = make_float4(u0.x, u0.y, u1.x, u1.y);
            float4 o1 = make_float4(u2.x, u2.y, u3.x, u3.y);
            if (accumulate) {
                float4 c0 = *(float4*)crow;
                float4 c1 = *(float4*)(crow + 4);
                o0 = make_float4(o0.x + c0.x, o0.y + c0.y, o0.z + c0.z, o0.w + c0.w);
                o1 = make_float4(o1.x + c1.x, o1.y + c1.y, o1.z + c1.z, o1.w + c1.w);
            }
            *(float4*)crow       = o0;
            *(float4*)(crow + 4) = o1;
        }
    }
}

// h = emb + relu(h_pre + Bias); pads -> 0.
__global__ void h_kernel(const float* __restrict__ Bias) {
    size_t i = (size_t)blockIdx.x * blockDim.x + threadIdx.x;
    if (i >= (size_t)E_N * SD) return;
    int d = (int)(i % SD);
    if (d < D_N) {
        float pre = g_A1[i] + Bias[d];
        g_A2[i] = g_emb[i] + fmaxf(pre, 0.f);
    } else {
        g_A2[i] = 0.f;
    }
}

__global__ void highway_kernel(const float* __restrict__ bg,
                               const float* __restrict__ L1buf,
                               const float* __restrict__ Gbuf,
                               const float* __restrict__ GCNbuf,
                               float* __restrict__ Outbuf) {
    size_t i = (size_t)blockIdx.x * blockDim.x + threadIdx.x;
    if (i >= (size_t)E_N * SD) return;
    int d = (int)(i % SD);
    if (d < D_N) {
        float tg = 1.0f / (1.0f + expf(-(Gbuf[i] + bg[d])));
        float l2 = fmaxf(GCNbuf[i], 0.f);
        Outbuf[i] = tg * l2 + (1.0f - tg) * L1buf[i];
    } else {
        Outbuf[i] = 0.f;
    }
}

// Fused hinge loss: one block per pair t. l_x/r_x cached in smem, Dm inline,
// 25 negatives split over 8 warps; one atomicAdd per block.
__global__ __launch_bounds__(256) void loss_kernel(const int* __restrict__ pl,
                                                   const int* __restrict__ pr,
                                                   const int* __restrict__ nr,
                                                   const int* __restrict__ nl,
                                                   const float* __restrict__ mask,
                                                   const float* __restrict__ node,
                                                   float* __restrict__ out) {
    __shared__ float4 sl[D4], sr[D4];
    __shared__ float wpart[8];
    __shared__ float s_dm;
    int t    = blockIdx.x;
    int tid  = threadIdx.x;
    int lane = tid & 31;
    int wid  = tid >> 5;

    const float4* xl = (const float4*)(node + (size_t)pl[t] * SD);
    const float4* xr = (const float4*)(node + (size_t)pr[t] * SD);
    float d = 0.f;
    if (tid < D4) {
        float4 a = xl[tid], b = xr[tid];
        sl[tid] = a; sr[tid] = b;
        d = fabsf(a.x - b.x) + fabsf(a.y - b.y) + fabsf(a.z - b.z) + fabsf(a.w - b.w);
    }
    d = warp_sum(d);
    if (lane == 0) wpart[wid] = d;
    __syncthreads();
    if (tid == 0) s_dm = wpart[0] + wpart[1] + wpart[2] + GAMMA_F;
    __syncthreads();
    float dm = s_dm;

    float hsum = 0.f;
    for (int k = wid; k < K_N; k += 8) {
        int i = t * K_N + k;
        const float4* xR = (const float4*)(node + (size_t)nr[i] * SD);
        const float4* xL = (const float4*)(node + (size_t)nl[i] * SD);
        float s1 = 0.f, s2 = 0.f;
#pragma unroll
        for (int it = 0; it < 3; it++) {
            int j = lane + it * 32;
            if (j < D4) {
                float4 a = sl[j], b = sr[j], cr = xR[j], cl = xL[j];
                s1 += fabsf(a.x - cr.x) + fabsf(a.y - cr.y) + fabsf(a.z - cr.z) + fabsf(a.w - cr.w);
                s2 += fabsf(cl.x - b.x) + fabsf(cl.y - b.y) + fabsf(cl.z - b.z) + fabsf(cl.w - b.w);
            }
        }
        s1 = warp_sum(s1);
        s2 = warp_sum(s2);
        if (lane == 0) hsum += (fmaxf(dm - s1, 0.f) + fmaxf(dm - s2, 0.f)) * mask[i];
    }
    if (lane == 0) wpart[wid] = hsum;
    __syncthreads();
    if (tid == 0) {
        float tot = 0.f;
#pragma unroll
        for (int w = 0; w < 8; w++) tot += wpart[w];
        atomicAdd(out, tot * 0.5f);
    }
}

// ---------------- host ----------------
extern "C" void kernel_launch(void* const* d_in, const int* in_sizes, int n_in,
                              void* d_out, int out_size) {
    const float* we    = (const float*)d_in[0];
    const float* kgw   = (const float*)d_in[1];
    const float* bg    = (const float*)d_in[2];
    const float* W1    = (const float*)d_in[3];
    const float* W2    = (const float*)d_in[4];
    const float* Dense = (const float*)d_in[5];
    const float* Bias  = (const float*)d_in[6];
    const int*   hr_rows = (const int*)d_in[7];
    const int*   hr_cols = (const int*)d_in[8];
    const float* hr_vals = (const float*)d_in[9];
    const int*   tr_rows = (const int*)d_in[10];
    const int*   tr_cols = (const int*)d_in[11];
    const float* tr_vals = (const float*)d_in[12];
    const int*   er_rows = (const int*)d_in[13];
    const int*   er_cols = (const int*)d_in[14];
    const float* er_vals = (const float*)d_in[15];
    const int*   adj_rows = (const int*)d_in[16];
    const int*   adj_cols = (const int*)d_in[17];
    const float* adj_vals = (const float*)d_in[18];
    const int*   pos_left  = (const int*)d_in[19];
    const int*   pos_right = (const int*)d_in[20];
    const int*   neg_right = (const int*)d_in[21];
    const int*   neg_left  = (const int*)d_in[22];
    const float* mask      = (const float*)d_in[23];
    float* out = (float*)d_out;

    int nnz_hr  = in_sizes[7];
    int nnz_tr  = in_sizes[10];
    int nnz_er  = in_sizes[13];
    int nnz_adj = in_sizes[16];

    float *p_emb, *p_A1, *p_A2, *p_A3, *p_A4, *p_A5, *p_A6, *p_Lm, *p_Rm, *p_P, *p_Wt;
    cudaGetSymbolAddress((void**)&p_emb, g_emb);
    cudaGetSymbolAddress((void**)&p_A1,  g_A1);
    cudaGetSymbolAddress((void**)&p_A2,  g_A2);
    cudaGetSymbolAddress((void**)&p_A3,  g_A3);
    cudaGetSymbolAddress((void**)&p_A4,  g_A4);
    cudaGetSymbolAddress((void**)&p_A5,  g_A5);
    cudaGetSymbolAddress((void**)&p_A6,  g_A6);
    cudaGetSymbolAddress((void**)&p_Lm,  g_Lm);
    cudaGetSymbolAddress((void**)&p_Rm,  g_Rm);
    cudaGetSymbolAddress((void**)&p_P,   g_P);
    cudaGetSymbolAddress((void**)&p_Wt,  g_Wt);

    const int ELEM = E_N * SD;
    const int EW_BLOCKS = (ELEM + 255) / 256;
    dim3 gemmGridE(SD / BN, (E_N + BM - 1) / BM);   // (5, 391): cols fast -> A reuse in L2
    dim3 gemmGridR(SD / BN, (R_N + BM - 1) / BM);   // (5, 4)

    zero_out_kernel<<<1, 1>>>(out);
    pad_weights_kernel<<<(6 * SD * SD + 255) / 256, 256>>>(Dense, W1, W2, kgw);
    normalize_kernel<<<(E_N * 32) / 256, 256>>>(we);

    // relation aggregation: L, Rm
    zero4_kernel<<<(R_N * SD / 4 + 255) / 256, 256>>>((float4*)p_Lm, R_N * SD / 4);
    zero4_kernel<<<(R_N * SD / 4 + 255) / 256, 256>>>((float4*)p_Rm, R_N * SD / 4);
    spmm_kernel<<<(nnz_hr + 7) / 8, 256>>>(hr_rows, hr_cols, hr_vals, nnz_hr, p_emb, p_Lm, 0);
    spmm_kernel<<<(nnz_tr + 7) / 8, 256>>>(tr_rows, tr_cols, tr_vals, nnz_tr, p_emb, p_Rm, 0);

    // P = L @ Db1 + Rm @ Db2  (Dense_bot pushed through the er-spmm)
    sgemm_kernel<<<gemmGridR, 256>>>(p_Lm, p_Wt + 1 * SD * SD, p_P, R_N, 0);
    sgemm_kernel<<<gemmGridR, 256>>>(p_Rm, p_Wt + 2 * SD * SD, p_P, R_N, 1);

    // h_pre = emb @ Dense_top + spmm(er, +-P)
    sgemm_kernel<<<gemmGridE, 256>>>(p_emb, p_Wt + 0 * SD * SD, p_A1, E_N, 0);
    spmm_kernel<<<(nnz_er + 7) / 8, 256>>>(er_rows, er_cols, er_vals, nnz_er, p_P, p_A1, 1);

    // h = emb + relu(h_pre + Bias)
    h_kernel<<<EW_BLOCKS, 256>>>(Bias);

    // layer 1
    sgemm_kernel<<<gemmGridE, 256>>>(p_A2, p_Wt + 3 * SD * SD, p_A3, E_N, 0);
    sgemm_kernel<<<gemmGridE, 256>>>(p_A2, p_Wt + 5 * SD * SD, p_A4, E_N, 0);
    zero4_kernel<<<(ELEM / 4 + 255) / 256, 256>>>((float4*)p_A5, ELEM / 4);
    spmm_kernel<<<(nnz_adj + 7) / 8, 256>>>(adj_rows, adj_cols, adj_vals, nnz_adj, p_A3, p_A5, 0);
    highway_kernel<<<EW_BLOCKS, 256>>>(bg, p_A2, p_A4, p_A5, p_A6);

    // layer 2
    sgemm_kernel<<<gemmGridE, 256>>>(p_A6, p_Wt + 4 * SD * SD, p_A3, E_N, 0);
    sgemm_kernel<<<gemmGridE, 256>>>(p_A6, p_Wt + 5 * SD * SD, p_A4, E_N, 0);
    zero4_kernel<<<(ELEM / 4 + 255) / 256, 256>>>((float4*)p_A1, ELEM / 4);
    spmm_kernel<<<(nnz_adj + 7) / 8, 256>>>(adj_rows, adj_cols, adj_vals, nnz_adj, p_A3, p_A1, 0);
    highway_kernel<<<EW_BLOCKS, 256>>>(bg, p_A6, p_A4, p_A1, p_A2);   // node -> g_A2

    // fused loss (Dm inline)
    loss_kernel<<<T_N, 256>>>(pos_left, pos_right, neg_right, neg_left, mask, p_A2, out);
    (void)n_in; (void)out_size;
}

// round 7
// speedup vs baseline: 1.0936x; 1.0933x over previous
#include <cuda_runtime.h>
#include <math.h>

#define E_N 100000
#define D_N 300
#define R_N 1000
#define T_N 10000
#define K_N 25
#define SD  320           // padded row stride (floats)
#define D4  75            // 300/4 float4 per real row
#define SD4 80            // 320/4 float4 per padded row
#define GAMMA_F 1.0f

// ---------------- scratch (device globals: allocation-free) ----------------
__device__ float g_emb[(size_t)E_N * SD];
__device__ float g_A1 [(size_t)E_N * SD];
__device__ float g_A2 [(size_t)E_N * SD];
__device__ float g_A3 [(size_t)E_N * SD];
__device__ float g_A5 [(size_t)E_N * SD];
__device__ float g_A6 [(size_t)E_N * SD];
__device__ float g_Lm [R_N * SD];
__device__ float g_Rm [R_N * SD];
__device__ float g_P  [R_N * SD];
__device__ float g_Wt [6 * SD * SD];   // 0:Dt 1:Db1 2:Db2 3:W1 4:W2 5:KG

// ---------------- helpers ----------------
__device__ __forceinline__ float warp_sum(float v) {
#pragma unroll
    for (int o = 16; o > 0; o >>= 1) v += __shfl_xor_sync(0xffffffffu, v, o);
    return v;
}

__device__ __forceinline__ unsigned long long bcast2(float x) {
    unsigned long long r;
    asm("mov.b64 %0, {%1, %1};" : "=l"(r) : "f"(x));
    return r;
}
__device__ __forceinline__ float2 unpack2(unsigned long long v) {
    float2 f;
    asm("mov.b64 {%0, %1}, %2;" : "=f"(f.x), "=f"(f.y) : "l"(v));
    return f;
}
__device__ __forceinline__ void ffma2(unsigned long long& d, unsigned long long a, unsigned long long b) {
    asm("fma.rn.f32x2 %0, %1, %2, %0;" : "+l"(d) : "l"(a), "l"(b));
}
__device__ __forceinline__ void red_add_v4(float* p, float a, float b, float c, float d) {
    asm volatile("red.global.add.v4.f32 [%0], {%1, %2, %3, %4};"
                 :: "l"(p), "f"(a), "f"(b), "f"(c), "f"(d) : "memory");
}

// ---------------- small kernels ----------------
__global__ void zero_out_kernel(float* out) { if (threadIdx.x == 0 && blockIdx.x == 0) out[0] = 0.0f; }

__global__ void zero4_kernel(float4* p, int n4) {
    int i = blockIdx.x * blockDim.x + threadIdx.x;
    if (i < n4) p[i] = make_float4(0.f, 0.f, 0.f, 0.f);
}

__global__ void pad_weights_kernel(const float* __restrict__ Dense,
                                   const float* __restrict__ W1,
                                   const float* __restrict__ W2,
                                   const float* __restrict__ KG) {
    int idx = blockIdx.x * blockDim.x + threadIdx.x;
    const int total = 6 * SD * SD;
    if (idx >= total) return;
    int w   = idx / (SD * SD);
    int rem = idx % (SD * SD);
    int r = rem / SD, c = rem % SD;
    float v = 0.f;
    if (r < D_N && c < D_N) {
        if      (w == 0) v = Dense[(size_t)r * D_N + c];
        else if (w == 1) v = Dense[(size_t)(D_N + r) * D_N + c];
        else if (w == 2) v = Dense[(size_t)(2 * D_N + r) * D_N + c];
        else if (w == 3) v = W1[(size_t)r * D_N + c];
        else if (w == 4) v = W2[(size_t)r * D_N + c];
        else             v = KG[(size_t)r * D_N + c];
    }
    g_Wt[idx] = v;
}

__global__ void normalize_kernel(const float* __restrict__ we) {
    int warp = (blockIdx.x * blockDim.x + threadIdx.x) >> 5;
    int lane = threadIdx.x & 31;
    if (warp >= E_N) return;
    const float4* src = (const float4*)(we + (size_t)warp * D_N);
    float4 v[3];
    float s = 0.f;
#pragma unroll
    for (int it = 0; it < 3; it++) {
        int j = lane + it * 32;
        if (j < D4) {
            float4 x = src[j];
            v[it] = x;
            s += x.x * x.x + x.y * x.y + x.z * x.z + x.w * x.w;
        } else {
            v[it] = make_float4(0.f, 0.f, 0.f, 0.f);
        }
    }
    s = warp_sum(s);
    float inv = 1.0f / sqrtf(s);
    float4* dst = (float4*)(g_emb + (size_t)warp * SD);
#pragma unroll
    for (int it = 0; it < 3; it++) {
        int j = lane + it * 32;
        if (j < D4)       dst[j] = make_float4(v[it].x * inv, v[it].y * inv, v[it].z * inv, v[it].w * inv);
        else if (j < SD4) dst[j] = make_float4(0.f, 0.f, 0.f, 0.f);
    }
}

// COO SpMM scatter with vector reductions. Warp per nnz.
__global__ void spmm_kernel(const int* __restrict__ rows, const int* __restrict__ cols,
                            const float* __restrict__ vals, int nnz,
                            const float* __restrict__ X, float* __restrict__ Out,
                            int rel_mode) {
    int warp = (blockIdx.x * blockDim.x + threadIdx.x) >> 5;
    int lane = threadIdx.x & 31;
    if (warp >= nnz) return;
    int   r = rows[warp];
    int   c = cols[warp];
    float v = vals[warp];
    if (rel_mode && c >= R_N) { c -= R_N; v = -v; }
    const float4* xr = (const float4*)(X + (size_t)c * SD);
    float* orow = Out + (size_t)r * SD;
#pragma unroll
    for (int it = 0; it < 3; it++) {
        int j = lane + it * 32;
        if (j < D4) {
            float4 x = xr[j];
            red_add_v4(orow + j * 4, v * x.x, v * x.y, v * x.z, v * x.w);
        }
    }
}

// ---------------- SGEMM (packed f32x2, double-buffered): C = A[M,304] @ B[304,320] ----------------
// mode 0: store; mode 1: C += ; mode 3: highway epilogue
//   tg = sigmoid(acc + epv[d]); C = tg*relu(ep2) + (1-tg)*ep1 ; pads -> 0
#define BM 256
#define BN 64
#define BK 16
#define KTILES 19   // K = 304 >= 300, pad cols 300..303 are guaranteed zero
__global__ __launch_bounds__(256, 2) void sgemm_kernel(const float* __restrict__ A,
                                                       const float* __restrict__ B,
                                                       float* __restrict__ C,
                                                       int M, int mode,
                                                       const float* __restrict__ ep1,
                                                       const float* __restrict__ ep2,
                                                       const float* __restrict__ epv) {
    __shared__ float As[2][BK][BM];
    __shared__ float Bs[2][BK][BN];
    int bm = blockIdx.y * BM;
    int bn = blockIdx.x * BN;
    int tid = threadIdx.x;
    int tx = tid & 7;      // 8 col-groups of 8
    int ty = tid >> 3;     // 32 row-groups of 8
    int arow = bm + tid;
    bool avalid = arow < M;
    const float* Aptr = A + (size_t)arow * SD;
    int brow  = tid >> 4;  // 0..15
    int bcol4 = tid & 15;
    const float* Bptr = B + (size_t)brow * SD + bn + bcol4 * 4;

    unsigned long long acc[8][4];
#pragma unroll
    for (int i = 0; i < 8; i++)
#pragma unroll
        for (int j = 0; j < 4; j++) acc[i][j] = 0ull;

    float4 ra[4], rb;
    // prologue: tile 0 -> stage 0
#pragma unroll
    for (int c = 0; c < 4; c++)
        ra[c] = avalid ? *(const float4*)(Aptr + c * 4) : make_float4(0.f, 0.f, 0.f, 0.f);
    rb = *(const float4*)(Bptr);
#pragma unroll
    for (int c = 0; c < 4; c++) {
        As[0][c * 4 + 0][tid] = ra[c].x;
        As[0][c * 4 + 1][tid] = ra[c].y;
        As[0][c * 4 + 2][tid] = ra[c].z;
        As[0][c * 4 + 3][tid] = ra[c].w;
    }
    *(float4*)(&Bs[0][brow][bcol4 * 4]) = rb;
    __syncthreads();

    for (int t = 0; t < KTILES; t++) {
        int cur = t & 1, nxt = cur ^ 1;
        if (t + 1 < KTILES) {
            int k0 = (t + 1) * BK;
#pragma unroll
            for (int c = 0; c < 4; c++)
                ra[c] = avalid ? *(const float4*)(Aptr + k0 + c * 4) : make_float4(0.f, 0.f, 0.f, 0.f);
            rb = *(const float4*)(Bptr + (size_t)k0 * SD);
        }
#pragma unroll
        for (int k = 0; k < BK; k++) {
            ulonglong2 bb0 = *(const ulonglong2*)(&Bs[cur][k][tx * 8]);
            ulonglong2 bb1 = *(const ulonglong2*)(&Bs[cur][k][tx * 8 + 4]);
            unsigned long long b2[4] = {bb0.x, bb0.y, bb1.x, bb1.y};
            float4 a0 = *(const float4*)(&As[cur][k][ty * 8]);
            float4 a1 = *(const float4*)(&As[cur][k][ty * 8 + 4]);
            unsigned long long a2[8];
            a2[0] = bcast2(a0.x); a2[1] = bcast2(a0.y); a2[2] = bcast2(a0.z); a2[3] = bcast2(a0.w);
            a2[4] = bcast2(a1.x); a2[5] = bcast2(a1.y); a2[6] = bcast2(a1.z); a2[7] = bcast2(a1.w);
#pragma unroll
            for (int i = 0; i < 8; i++)
#pragma unroll
                for (int j = 0; j < 4; j++)
                    ffma2(acc[i][j], a2[i], b2[j]);
        }
        if (t + 1 < KTILES) {
#pragma unroll
            for (int c = 0; c < 4; c++) {
                As[nxt][c * 4 + 0][tid] = ra[c].x;
                As[nxt][c * 4 + 1][tid] = ra[c].y;
                As[nxt][c * 4 + 2][tid] = ra[c].z;
                As[nxt][c * 4 + 3][tid] = ra[c].w;
            }
            *(float4*)(&Bs[nxt][brow][bcol4 * 4]) = rb;
        }
        __syncthreads();
    }

    int gcol = bn + tx * 8;
#pragma unroll
    for (int i = 0; i < 8; i++) {
        int grow = bm + ty * 8 + i;
        if (grow >= M) continue;
        float2 u0 = unpack2(acc[i][0]);
        float2 u1 = unpack2(acc[i][1]);
        float2 u2 = unpack2(acc[i][2]);
        float2 u3 = unpack2(acc[i][3]);
        float vals[8] = {u0.x, u0.y, u1.x, u1.y, u2.x, u2.y, u3.x, u3.y};
        float* crow = C + (size_t)grow * SD + gcol;
        if (mode == 0) {
            *(float4*)crow       = make_float4(vals[0], vals[1], vals[2], vals[3]);
            *(float4*)(crow + 4) = make_float4(vals[4], vals[5], vals[6], vals[7]);
        } else if (mode == 1) {
            float4 c0 = *(float4*)crow;
            float4 c1 = *(float4*)(crow + 4);
            *(float4*)crow       = make_float4(c0.x + vals[0], c0.y + vals[1], c0.z + vals[2], c0.w + vals[3]);
            *(float4*)(crow + 4) = make_float4(c1.x + vals[4], c1.y + vals[5], c1.z + vals[6], c1.w + vals[7]);
        } else {
            const float* l1 = ep1 + (size_t)grow * SD + gcol;
            const float* gc = ep2 + (size_t)grow * SD + gcol;
#pragma unroll
            for (int j = 0; j < 8; j++) {
                int d = gcol + j;
                float o = 0.f;
                if (d < D_N) {
                    float tg = 1.0f / (1.0f + expf(-(vals[j] + epv[d])));
                    float g  = fmaxf(gc[j], 0.f);
                    o = tg * g + (1.0f - tg) * l1[j];
                }
                crow[j] = o;
            }
        }
    }
}

// h = emb + relu(h_pre + Bias); pads -> 0. float4-vectorized.
__global__ void h_kernel(const float* __restrict__ Bias) {
    int i = blockIdx.x * blockDim.x + threadIdx.x;     // float4 index
    if (i >= E_N * SD4) return;
    int j = i % SD4;
    float4 o = make_float4(0.f, 0.f, 0.f, 0.f);
    if (j < D4) {
        float4 p = ((const float4*)g_A1)[i];
        float4 e = ((const float4*)g_emb)[i];
        int d = j * 4;
        o.x = e.x + fmaxf(p.x + Bias[d + 0], 0.f);
        o.y = e.y + fmaxf(p.y + Bias[d + 1], 0.f);
        o.z = e.z + fmaxf(p.z + Bias[d + 2], 0.f);
        o.w = e.w + fmaxf(p.w + Bias[d + 3], 0.f);
    }
    ((float4*)g_A2)[i] = o;
}

// Fused hinge loss: one block per pair t.
__global__ __launch_bounds__(256) void loss_kernel(const int* __restrict__ pl,
                                                   const int* __restrict__ pr,
                                                   const int* __restrict__ nr,
                                                   const int* __restrict__ nl,
                                                   const float* __restrict__ mask,
                                                   const float* __restrict__ node,
                                                   float* __restrict__ out) {
    __shared__ float4 sl[D4], sr[D4];
    __shared__ float wpart[8];
    __shared__ float s_dm;
    int t    = blockIdx.x;
    int tid  = threadIdx.x;
    int lane = tid & 31;
    int wid  = tid >> 5;

    const float4* xl = (const float4*)(node + (size_t)pl[t] * SD);
    const float4* xr = (const float4*)(node + (size_t)pr[t] * SD);
    float d = 0.f;
    if (tid < D4) {
        float4 a = xl[tid], b = xr[tid];
        sl[tid] = a; sr[tid] = b;
        d = fabsf(a.x - b.x) + fabsf(a.y - b.y) + fabsf(a.z - b.z) + fabsf(a.w - b.w);
    }
    d = warp_sum(d);
    if (lane == 0) wpart[wid] = d;
    __syncthreads();
    if (tid == 0) s_dm = wpart[0] + wpart[1] + wpart[2] + GAMMA_F;
    __syncthreads();
    float dm = s_dm;

    float hsum = 0.f;
    for (int k = wid; k < K_N; k += 8) {
        int i = t * K_N + k;
        const float4* xR = (const float4*)(node + (size_t)nr[i] * SD);
        const float4* xL = (const float4*)(node + (size_t)nl[i] * SD);
        float s1 = 0.f, s2 = 0.f;
#pragma unroll
        for (int it = 0; it < 3; it++) {
            int j = lane + it * 32;
            if (j < D4) {
                float4 a = sl[j], b = sr[j], cr = xR[j], cl = xL[j];
                s1 += fabsf(a.x - cr.x) + fabsf(a.y - cr.y) + fabsf(a.z - cr.z) + fabsf(a.w - cr.w);
                s2 += fabsf(cl.x - b.x) + fabsf(cl.y - b.y) + fabsf(cl.z - b.z) + fabsf(cl.w - b.w);
            }
        }
        s1 = warp_sum(s1);
        s2 = warp_sum(s2);
        if (lane == 0) hsum += (fmaxf(dm - s1, 0.f) + fmaxf(dm - s2, 0.f)) * mask[i];
    }
    if (lane == 0) wpart[wid] = hsum;
    __syncthreads();
    if (tid == 0) {
        float tot = 0.f;
#pragma unroll
        for (int w = 0; w < 8; w++) tot += wpart[w];
        atomicAdd(out, tot * 0.5f);
    }
}

// ---------------- host ----------------
extern "C" void kernel_launch(void* const* d_in, const int* in_sizes, int n_in,
                              void* d_out, int out_size) {
    const float* we    = (const float*)d_in[0];
    const float* kgw   = (const float*)d_in[1];
    const float* bg    = (const float*)d_in[2];
    const float* W1    = (const float*)d_in[3];
    const float* W2    = (const float*)d_in[4];
    const float* Dense = (const float*)d_in[5];
    const float* Bias  = (const float*)d_in[6];
    const int*   hr_rows = (const int*)d_in[7];
    const int*   hr_cols = (const int*)d_in[8];
    const float* hr_vals = (const float*)d_in[9];
    const int*   tr_rows = (const int*)d_in[10];
    const int*   tr_cols = (const int*)d_in[11];
    const float* tr_vals = (const float*)d_in[12];
    const int*   er_rows = (const int*)d_in[13];
    const int*   er_cols = (const int*)d_in[14];
    const float* er_vals = (const float*)d_in[15];
    const int*   adj_rows = (const int*)d_in[16];
    const int*   adj_cols = (const int*)d_in[17];
    const float* adj_vals = (const float*)d_in[18];
    const int*   pos_left  = (const int*)d_in[19];
    const int*   pos_right = (const int*)d_in[20];
    const int*   neg_right = (const int*)d_in[21];
    const int*   neg_left  = (const int*)d_in[22];
    const float* mask      = (const float*)d_in[23];
    float* out = (float*)d_out;

    int nnz_hr  = in_sizes[7];
    int nnz_tr  = in_sizes[10];
    int nnz_er  = in_sizes[13];
    int nnz_adj = in_sizes[16];

    float *p_emb, *p_A1, *p_A2, *p_A3, *p_A5, *p_A6, *p_Lm, *p_Rm, *p_P, *p_Wt;
    cudaGetSymbolAddress((void**)&p_emb, g_emb);
    cudaGetSymbolAddress((void**)&p_A1,  g_A1);
    cudaGetSymbolAddress((void**)&p_A2,  g_A2);
    cudaGetSymbolAddress((void**)&p_A3,  g_A3);
    cudaGetSymbolAddress((void**)&p_A5,  g_A5);
    cudaGetSymbolAddress((void**)&p_A6,  g_A6);
    cudaGetSymbolAddress((void**)&p_Lm,  g_Lm);
    cudaGetSymbolAddress((void**)&p_Rm,  g_Rm);
    cudaGetSymbolAddress((void**)&p_P,   g_P);
    cudaGetSymbolAddress((void**)&p_Wt,  g_Wt);

    const int ELEM = E_N * SD;
    dim3 gemmGridE(SD / BN, (E_N + BM - 1) / BM);   // (5, 391): cols fast -> A reuse in L2
    dim3 gemmGridR(SD / BN, (R_N + BM - 1) / BM);   // (5, 4)

    // launches 1-5 (launch #6 = big GEMM, so ncu -s 5 -c 1 profiles it)
    zero_out_kernel<<<1, 1>>>(out);
    pad_weights_kernel<<<(6 * SD * SD + 255) / 256, 256>>>(Dense, W1, W2, kgw);
    normalize_kernel<<<(E_N * 32) / 256, 256>>>(we);
    zero4_kernel<<<(R_N * SD / 4 + 255) / 256, 256>>>((float4*)p_Lm, R_N * SD / 4);
    zero4_kernel<<<(R_N * SD / 4 + 255) / 256, 256>>>((float4*)p_Rm, R_N * SD / 4);

    // 6: h_pre partial = emb @ Dense_top -> A1   (PROFILED LAUNCH)
    sgemm_kernel<<<gemmGridE, 256>>>(p_emb, p_Wt + 0 * SD * SD, p_A1, E_N, 0, 0, 0, 0);

    // relation aggregation: L, Rm
    spmm_kernel<<<(nnz_hr + 7) / 8, 256>>>(hr_rows, hr_cols, hr_vals, nnz_hr, p_emb, p_Lm, 0);
    spmm_kernel<<<(nnz_tr + 7) / 8, 256>>>(tr_rows, tr_cols, tr_vals, nnz_tr, p_emb, p_Rm, 0);

    // P = L @ Db1 + Rm @ Db2  (Dense_bot pushed through the er-spmm)
    sgemm_kernel<<<gemmGridR, 256>>>(p_Lm, p_Wt + 1 * SD * SD, p_P, R_N, 0, 0, 0, 0);
    sgemm_kernel<<<gemmGridR, 256>>>(p_Rm, p_Wt + 2 * SD * SD, p_P, R_N, 1, 0, 0, 0);

    // h_pre += spmm(er, +-P)
    spmm_kernel<<<(nnz_er + 7) / 8, 256>>>(er_rows, er_cols, er_vals, nnz_er, p_P, p_A1, 1);

    // h = emb + relu(h_pre + Bias)
    h_kernel<<<(E_N * SD4 + 255) / 256, 256>>>(Bias);

    // layer 1: t1 = h@W1 -> A3; gcn1 accum in A5; gate GEMM fuses highway -> A6
    sgemm_kernel<<<gemmGridE, 256>>>(p_A2, p_Wt + 3 * SD * SD, p_A3, E_N, 0, 0, 0, 0);
    zero4_kernel<<<(ELEM / 4 + 255) / 256, 256>>>((float4*)p_A5, ELEM / 4);
    spmm_kernel<<<(nnz_adj + 7) / 8, 256>>>(adj_rows, adj_cols, adj_vals, nnz_adj, p_A3, p_A5, 0);
    sgemm_kernel<<<gemmGridE, 256>>>(p_A2, p_Wt + 5 * SD * SD, p_A6, E_N, 3, p_A2, p_A5, bg);

    // layer 2: t2 = hg1@W2 -> A3; gcn2 accum in A1; gate GEMM fuses highway -> node (A2)
    sgemm_kernel<<<gemmGridE, 256>>>(p_A6, p_Wt + 4 * SD * SD, p_A3, E_N, 0, 0, 0, 0);
    zero4_kernel<<<(ELEM / 4 + 255) / 256, 256>>>((float4*)p_A1, ELEM / 4);
    spmm_kernel<<<(nnz_adj + 7) / 8, 256>>>(adj_rows, adj_cols, adj_vals, nnz_adj, p_A3, p_A1, 0);
    sgemm_kernel<<<gemmGridE, 256>>>(p_A6, p_Wt + 5 * SD * SD, p_A2, E_N, 3, p_A6, p_A1, bg);

    // fused loss
    loss_kernel<<<T_N, 256>>>(pos_left, pos_right, neg_right, neg_left, mask, p_A2, out);
    (void)n_in; (void)out_size;
}